// round 2
// baseline (speedup 1.0000x reference)
#include <cuda_runtime.h>
#include <math.h>

#define B 4
#define N 8192
#define M 8192
#define EPS 1e-8f
#define TS 256  // tile size in both dims

// Scratch: per-point squared-distance minima, as int bit patterns (valid
// ordering because all values >= 0).
__device__ int g_rowmin[B * N];
__device__ int g_colmin[B * M];

// ---------------- packed f32x2 helpers ----------------
__device__ __forceinline__ unsigned long long pk2(float a, float b) {
    unsigned long long r;
    asm("mov.b64 %0, {%1, %2};" : "=l"(r) : "f"(a), "f"(b));
    return r;
}
__device__ __forceinline__ unsigned long long add2(unsigned long long a, unsigned long long b) {
    unsigned long long r;
    asm("add.rn.f32x2 %0, %1, %2;" : "=l"(r) : "l"(a), "l"(b));
    return r;
}
__device__ __forceinline__ unsigned long long mul2(unsigned long long a, unsigned long long b) {
    unsigned long long r;
    asm("mul.rn.f32x2 %0, %1, %2;" : "=l"(r) : "l"(a), "l"(b));
    return r;
}
__device__ __forceinline__ unsigned long long fma2(unsigned long long a, unsigned long long b,
                                                   unsigned long long c) {
    unsigned long long r;
    asm("fma.rn.f32x2 %0, %1, %2, %3;" : "=l"(r) : "l"(a), "l"(b), "l"(c));
    return r;
}
__device__ __forceinline__ void unpk2(unsigned long long v, float& lo, float& hi) {
    asm("mov.b64 {%0, %1}, %2;" : "=f"(lo), "=f"(hi) : "l"(v));
}

// ---------------- init ----------------
__global__ void init_kernel(float* out) {
    int tid = blockIdx.x * blockDim.x + threadIdx.x;
    const int INF_BITS = 0x7F800000;  // +inf
    if (tid < B * N) g_rowmin[tid] = INF_BITS;
    if (tid < B * M) g_colmin[tid] = INF_BITS;
    if (tid == 0) out[0] = 0.0f;
}

// ---------------- fused tile kernel ----------------
// Tile: 256 sources x 256 targets. 256 threads (16x16); each thread computes a
// 16x16 register sub-tile (16 rows x 8 f32x2 column-pairs).
__global__ __launch_bounds__(256, 2) void tile_kernel(const float* __restrict__ source,
                                                      const float* __restrict__ target) {
    __shared__ __align__(16) float s_x[TS], s_y[TS], s_z[TS];
    __shared__ __align__(16) float t_x[TS], t_y[TS], t_z[TS];  // NEGATED targets
    __shared__ float red[TS * 17];                             // padded, conflict-free

    const int tid = threadIdx.x;
    const int b   = blockIdx.z;
    const int row0 = blockIdx.y * TS;  // source tile base
    const int col0 = blockIdx.x * TS;  // target tile base

    // Stage source tile (coordinate-split)
    const float* sp = source + ((long)b * N + row0) * 3;
    for (int idx = tid; idx < 3 * TS; idx += 256) {
        float v = sp[idx];
        int p = idx / 3, c = idx - 3 * p;
        if (c == 0) s_x[p] = v; else if (c == 1) s_y[p] = v; else s_z[p] = v;
    }
    // Stage target tile, negated (so sub == add in packed math)
    const float* tp = target + ((long)b * M + col0) * 3;
    for (int idx = tid; idx < 3 * TS; idx += 256) {
        float v = -tp[idx];
        int p = idx / 3, c = idx - 3 * p;
        if (c == 0) t_x[p] = v; else if (c == 1) t_y[p] = v; else t_z[p] = v;
    }
    __syncthreads();

    const int txi = tid & 15;
    const int tyi = tid >> 4;
    const int r0 = tyi * 16;  // local source rows r0..r0+15
    const int c0 = txi * 16;  // local target cols c0..c0+15

    // Load 8 target pairs per coordinate (LDS.64, broadcast across tyi)
    unsigned long long ntx[8], nty[8], ntz[8];
#pragma unroll
    for (int j = 0; j < 8; j++) {
        float2 vx = *reinterpret_cast<const float2*>(&t_x[c0 + 2 * j]);
        float2 vy = *reinterpret_cast<const float2*>(&t_y[c0 + 2 * j]);
        float2 vz = *reinterpret_cast<const float2*>(&t_z[c0 + 2 * j]);
        ntx[j] = pk2(vx.x, vx.y);
        nty[j] = pk2(vy.x, vy.y);
        ntz[j] = pk2(vz.x, vz.y);
    }

    float rmin[16], cmin[16];
#pragma unroll
    for (int i = 0; i < 16; i++) { rmin[i] = 3.4e38f; cmin[i] = 3.4e38f; }

#pragma unroll 4
    for (int i = 0; i < 16; i++) {
        float sx = s_x[r0 + i], sy = s_y[r0 + i], sz = s_z[r0 + i];
        unsigned long long sxd = pk2(sx, sx);
        unsigned long long syd = pk2(sy, sy);
        unsigned long long szd = pk2(sz, sz);
#pragma unroll
        for (int j = 0; j < 8; j++) {
            unsigned long long dx = add2(sxd, ntx[j]);   // s - t (targets negated)
            unsigned long long dy = add2(syd, nty[j]);
            unsigned long long dz = add2(szd, ntz[j]);
            unsigned long long d  = mul2(dx, dx);
            d = fma2(dy, dy, d);
            d = fma2(dz, dz, d);
            float dlo, dhi;
            unpk2(d, dlo, dhi);
            rmin[i]          = fminf(rmin[i], fminf(dlo, dhi));
            cmin[2 * j]      = fminf(cmin[2 * j], dlo);
            cmin[2 * j + 1]  = fminf(cmin[2 * j + 1], dhi);
        }
    }

    // ---- CTA reduction: row mins (across txi) ----
#pragma unroll
    for (int i = 0; i < 16; i++) red[(r0 + i) * 17 + txi] = rmin[i];
    __syncthreads();
    {
        float m = red[tid * 17];
#pragma unroll
        for (int k = 1; k < 16; k++) m = fminf(m, red[tid * 17 + k]);
        atomicMin(&g_rowmin[b * N + row0 + tid], __float_as_int(m));
    }
    __syncthreads();

    // ---- CTA reduction: col mins (across tyi) ----
#pragma unroll
    for (int k = 0; k < 16; k++) red[(c0 + k) * 17 + tyi] = cmin[k];
    __syncthreads();
    {
        float m = red[tid * 17];
#pragma unroll
        for (int k = 1; k < 16; k++) m = fminf(m, red[tid * 17 + k]);
        atomicMin(&g_colmin[b * M + col0 + tid], __float_as_int(m));
    }
}

// ---------------- finalize ----------------
// forward = mean over B*N of sqrt(rowmin+EPS)*w ; backward = mean over B*M of sqrt(colmin+EPS)
__global__ void finalize_kernel(const float* __restrict__ weights, float* __restrict__ out) {
    __shared__ float sred[256];
    int tid = blockIdx.x * blockDim.x + threadIdx.x;
    float v = 0.0f;
    if (tid < B * N) {
        float d2 = __int_as_float(g_rowmin[tid]);
        v = sqrtf(d2 + EPS) * weights[tid] * (1.0f / (B * N));
    } else {
        int t = tid - B * N;
        float d2 = __int_as_float(g_colmin[t]);
        v = sqrtf(d2 + EPS) * (1.0f / (B * M));
    }
    sred[threadIdx.x] = v;
    __syncthreads();
    for (int s = 128; s > 0; s >>= 1) {
        if (threadIdx.x < s) sred[threadIdx.x] += sred[threadIdx.x + s];
        __syncthreads();
    }
    if (threadIdx.x == 0) atomicAdd(out, sred[0]);
}

extern "C" void kernel_launch(void* const* d_in, const int* in_sizes, int n_in,
                              void* d_out, int out_size) {
    const float* source  = (const float*)d_in[0];
    const float* target  = (const float*)d_in[1];
    const float* weights = (const float*)d_in[2];
    float* out = (float*)d_out;

    init_kernel<<<(B * N + 255) / 256, 256>>>(out);

    dim3 grid(M / TS, N / TS, B);
    tile_kernel<<<grid, 256>>>(source, target);

    finalize_kernel<<<(B * N + B * M) / 256, 256>>>(weights, out);
}

// round 3
// speedup vs baseline: 1.1429x; 1.1429x over previous
#include <cuda_runtime.h>
#include <math.h>

#define B 4
#define N 8192
#define M 8192
#define EPS 1e-8f
#define TSR 256   // source rows per tile
#define TSC 128   // target cols per tile
#define CTILES (M / TSC)   // 64
#define RTILES (N / TSR)   // 32

// Per-tile partial minima (squared distances). Written with plain stores —
// no init kernel, no atomics.
__device__ float g_rowpart[B * CTILES * N];   // [b][colTile][row]
__device__ float g_colpart[B * RTILES * M];   // [b][rowTile][col]
__device__ float g_bsum[256];

// ---------------- packed f32x2 helpers ----------------
__device__ __forceinline__ unsigned long long pk2(float a, float b) {
    unsigned long long r;
    asm("mov.b64 %0, {%1, %2};" : "=l"(r) : "f"(a), "f"(b));
    return r;
}
__device__ __forceinline__ unsigned long long add2(unsigned long long a, unsigned long long b) {
    unsigned long long r;
    asm("add.rn.f32x2 %0, %1, %2;" : "=l"(r) : "l"(a), "l"(b));
    return r;
}
__device__ __forceinline__ unsigned long long fma2(unsigned long long a, unsigned long long b,
                                                   unsigned long long c) {
    unsigned long long r;
    asm("fma.rn.f32x2 %0, %1, %2, %3;" : "=l"(r) : "l"(a), "l"(b), "l"(c));
    return r;
}
__device__ __forceinline__ void unpk2(unsigned long long v, float& lo, float& hi) {
    asm("mov.b64 {%0, %1}, %2;" : "=f"(lo), "=f"(hi) : "l"(v));
}

// ---------------- fused tile kernel ----------------
// Tile: 256 sources x 128 targets. 256 threads (16 ty x 16 tx); each thread:
// 16 rows x 8 cols (4 f32x2 pairs). d^2 = ns + nt - 2 s.t
__global__ __launch_bounds__(256, 2) void tile_kernel(const float* __restrict__ source,
                                                      const float* __restrict__ target) {
    __shared__ __align__(16) float s_x[TSR], s_y[TSR], s_z[TSR], s_n[TSR];
    __shared__ __align__(16) float t2x[TSC], t2y[TSC], t2z[TSC], t_n[TSC];  // -2*t, ||t||^2
    __shared__ float red[TSR * 17];

    const int tid = threadIdx.x;
    const int b   = blockIdx.z;
    const int row0 = blockIdx.y * TSR;
    const int col0 = blockIdx.x * TSC;

    // Stage source tile: coords + norm
    {
        const float* sp = source + ((long)b * N + row0 + tid) * 3;
        float vx = sp[0], vy = sp[1], vz = sp[2];
        s_x[tid] = vx; s_y[tid] = vy; s_z[tid] = vz;
        s_n[tid] = vx * vx + vy * vy + vz * vz;
    }
    // Stage target tile: -2*coords + norm
    if (tid < TSC) {
        const float* tp = target + ((long)b * M + col0 + tid) * 3;
        float vx = tp[0], vy = tp[1], vz = tp[2];
        t2x[tid] = -2.0f * vx; t2y[tid] = -2.0f * vy; t2z[tid] = -2.0f * vz;
        t_n[tid] = vx * vx + vy * vy + vz * vz;
    }
    __syncthreads();

    const int txi = tid & 15;
    const int tyi = tid >> 4;
    const int r0 = tyi * 16;  // local rows r0..r0+15
    const int c0 = txi * 8;   // local cols c0..c0+7 (4 pairs)

    // Per-thread column constants: 4 pairs x {t2x, t2y, t2z, tn}
    unsigned long long ctx[4], cty[4], ctz[4], ctn[4];
#pragma unroll
    for (int j = 0; j < 4; j++) {
        float2 vx = *reinterpret_cast<const float2*>(&t2x[c0 + 2 * j]);
        float2 vy = *reinterpret_cast<const float2*>(&t2y[c0 + 2 * j]);
        float2 vz = *reinterpret_cast<const float2*>(&t2z[c0 + 2 * j]);
        float2 vn = *reinterpret_cast<const float2*>(&t_n[c0 + 2 * j]);
        ctx[j] = pk2(vx.x, vx.y);
        cty[j] = pk2(vy.x, vy.y);
        ctz[j] = pk2(vz.x, vz.y);
        ctn[j] = pk2(vn.x, vn.y);
    }

    float rmin[16], cmin[8];
#pragma unroll
    for (int i = 0; i < 16; i++) rmin[i] = 3.4e38f;
#pragma unroll
    for (int k = 0; k < 8; k++) cmin[k] = 3.4e38f;

#pragma unroll 4
    for (int i = 0; i < 16; i++) {
        float sx = s_x[r0 + i], sy = s_y[r0 + i], sz = s_z[r0 + i], sn = s_n[r0 + i];
        unsigned long long sxd = pk2(sx, sx);
        unsigned long long syd = pk2(sy, sy);
        unsigned long long szd = pk2(sz, sz);
        unsigned long long snd = pk2(sn, sn);
#pragma unroll
        for (int j = 0; j < 4; j++) {
            // q = nt - 2 s.t   (3 fma2)
            unsigned long long q = fma2(sxd, ctx[j], ctn[j]);
            q = fma2(syd, cty[j], q);
            q = fma2(szd, ctz[j], q);
            // p = d^2 = q + ns (1 add2)
            unsigned long long p = add2(q, snd);
            float plo, phi;
            unpk2(p, plo, phi);
            rmin[i]         = fminf(rmin[i], fminf(plo, phi));
            cmin[2 * j]     = fminf(cmin[2 * j], plo);
            cmin[2 * j + 1] = fminf(cmin[2 * j + 1], phi);
        }
    }

    // ---- CTA reduction: row mins (across txi), plain store to partials ----
#pragma unroll
    for (int i = 0; i < 16; i++) red[(r0 + i) * 17 + txi] = rmin[i];
    __syncthreads();
    {
        float m = red[tid * 17];
#pragma unroll
        for (int k = 1; k < 16; k++) m = fminf(m, red[tid * 17 + k]);
        g_rowpart[((long)b * CTILES + blockIdx.x) * N + row0 + tid] = m;
    }
    __syncthreads();

    // ---- CTA reduction: col mins (across tyi) ----
#pragma unroll
    for (int k = 0; k < 8; k++) red[(c0 + k) * 17 + tyi] = cmin[k];
    __syncthreads();
    if (tid < TSC) {
        float m = red[tid * 17];
#pragma unroll
        for (int k = 1; k < 16; k++) m = fminf(m, red[tid * 17 + k]);
        g_colpart[((long)b * RTILES + blockIdx.y) * M + col0 + tid] = m;
    }
}

// ---------------- finalize pass 1: reduce partials, block sums ----------------
__global__ void finalize1_kernel(const float* __restrict__ weights) {
    __shared__ float sred[256];
    int tid = blockIdx.x * blockDim.x + threadIdx.x;
    float v;
    if (tid < B * N) {
        int b = tid >> 13, row = tid & 8191;
        const float* p = &g_rowpart[((long)b * CTILES) * N + row];
        float m = p[0];
#pragma unroll 8
        for (int ct = 1; ct < CTILES; ct++) m = fminf(m, p[(long)ct * N]);
        v = sqrtf(m + EPS) * weights[tid] * (1.0f / (B * N));
    } else {
        int t = tid - B * N;
        int b = t >> 13, col = t & 8191;
        const float* p = &g_colpart[((long)b * RTILES) * M + col];
        float m = p[0];
#pragma unroll 8
        for (int rt = 1; rt < RTILES; rt++) m = fminf(m, p[(long)rt * M]);
        v = sqrtf(m + EPS) * (1.0f / (B * M));
    }
    sred[threadIdx.x] = v;
    __syncthreads();
    for (int s = 128; s > 0; s >>= 1) {
        if (threadIdx.x < s) sred[threadIdx.x] += sred[threadIdx.x + s];
        __syncthreads();
    }
    if (threadIdx.x == 0) g_bsum[blockIdx.x] = sred[0];
}

// ---------------- finalize pass 2: single block, plain store ----------------
__global__ void finalize2_kernel(float* __restrict__ out) {
    __shared__ float sred[256];
    sred[threadIdx.x] = g_bsum[threadIdx.x];
    __syncthreads();
    for (int s = 128; s > 0; s >>= 1) {
        if (threadIdx.x < s) sred[threadIdx.x] += sred[threadIdx.x + s];
        __syncthreads();
    }
    if (threadIdx.x == 0) out[0] = sred[0];
}

extern "C" void kernel_launch(void* const* d_in, const int* in_sizes, int n_in,
                              void* d_out, int out_size) {
    const float* source  = (const float*)d_in[0];
    const float* target  = (const float*)d_in[1];
    const float* weights = (const float*)d_in[2];
    float* out = (float*)d_out;

    dim3 grid(M / TSC, N / TSR, B);
    tile_kernel<<<grid, 256>>>(source, target);

    finalize1_kernel<<<(B * N + B * M) / 256, 256>>>(weights);
    finalize2_kernel<<<1, 256>>>(out);
}

// round 5
// speedup vs baseline: 1.3010x; 1.1384x over previous
#include <cuda_runtime.h>
#include <math.h>

#define B 4
#define N 8192
#define M 8192
#define EPS 1e-8f
#define TSR 256   // source rows per tile
#define TSC 128   // target cols per tile
#define CTILES (M / TSC)   // 64
#define RTILES (N / TSR)   // 32

typedef unsigned long long u64;

// Per-tile partial minima (squared distances). Plain stores — no init, no atomics.
__device__ float g_rowpart[B * CTILES * N];   // [b][colTile][row]
__device__ float g_colpart[B * RTILES * M];   // [b][rowTile][col]
__device__ float g_bsum[256];

// ---------------- packed f32x2 helpers ----------------
__device__ __forceinline__ u64 pk2(float a, float b) {
    u64 r;
    asm("mov.b64 %0, {%1, %2};" : "=l"(r) : "f"(a), "f"(b));
    return r;
}
__device__ __forceinline__ u64 add2(u64 a, u64 b) {
    u64 r;
    asm("add.rn.f32x2 %0, %1, %2;" : "=l"(r) : "l"(a), "l"(b));
    return r;
}
__device__ __forceinline__ u64 fma2(u64 a, u64 b, u64 c) {
    u64 r;
    asm("fma.rn.f32x2 %0, %1, %2, %3;" : "=l"(r) : "l"(a), "l"(b), "l"(c));
    return r;
}
__device__ __forceinline__ float2 u2f(u64 v) {
    float2 f;
    asm("mov.b64 {%0, %1}, %2;" : "=f"(f.x), "=f"(f.y) : "l"(v));
    return f;
}

// ---------------- fused tile kernel ----------------
// Tile: 256 sources x 128 targets. 256 threads (16 ty x 16 tx); each thread:
// 16 rows x 8 cols (4 f32x2 col-pairs). d^2 = (ns + nt) - 2 s.t (packed fma),
// mins via scalar FMNMX on the pair halves.
__global__ __launch_bounds__(256, 3) void tile_kernel(const float* __restrict__ source,
                                                      const float* __restrict__ target) {
    // Source rows staged as duplicated packed pairs (v,v): one LDS.64 -> ready reg.
    __shared__ __align__(16) u64 s_px[TSR], s_py[TSR], s_pz[TSR], s_pn[TSR];
    __shared__ __align__(16) float t2x[TSC], t2y[TSC], t2z[TSC], t_n[TSC];  // -2*t, ||t||^2
    __shared__ float red[TSR * 17];

    const int tid = threadIdx.x;
    const int b   = blockIdx.z;
    const int row0 = blockIdx.y * TSR;
    const int col0 = blockIdx.x * TSC;

    // Stage source tile: duplicated coords + norm
    {
        const float* sp = source + ((long)b * N + row0 + tid) * 3;
        float vx = sp[0], vy = sp[1], vz = sp[2];
        s_px[tid] = pk2(vx, vx);
        s_py[tid] = pk2(vy, vy);
        s_pz[tid] = pk2(vz, vz);
        float n = vx * vx + vy * vy + vz * vz;
        s_pn[tid] = pk2(n, n);
    }
    // Stage target tile: -2*coords + norm
    if (tid < TSC) {
        const float* tp = target + ((long)b * M + col0 + tid) * 3;
        float vx = tp[0], vy = tp[1], vz = tp[2];
        t2x[tid] = -2.0f * vx; t2y[tid] = -2.0f * vy; t2z[tid] = -2.0f * vz;
        t_n[tid] = vx * vx + vy * vy + vz * vz;
    }
    __syncthreads();

    const int txi = tid & 15;
    const int tyi = tid >> 4;
    const int r0 = tyi * 16;  // local rows r0..r0+15
    const int c0 = txi * 8;   // local cols c0..c0+7 (4 pairs)

    // Per-thread column constants: 4 pairs x {t2x, t2y, t2z, tn}
    u64 ctx[4], cty[4], ctz[4], ctn[4];
#pragma unroll
    for (int j = 0; j < 4; j++) {
        float2 vx = *reinterpret_cast<const float2*>(&t2x[c0 + 2 * j]);
        float2 vy = *reinterpret_cast<const float2*>(&t2y[c0 + 2 * j]);
        float2 vz = *reinterpret_cast<const float2*>(&t2z[c0 + 2 * j]);
        float2 vn = *reinterpret_cast<const float2*>(&t_n[c0 + 2 * j]);
        ctx[j] = pk2(vx.x, vx.y);
        cty[j] = pk2(vy.x, vy.y);
        ctz[j] = pk2(vz.x, vz.y);
        ctn[j] = pk2(vn.x, vn.y);
    }

    const float BIGF = 3.4e38f;
    float cl[8];
#pragma unroll
    for (int k = 0; k < 8; k++) cl[k] = BIGF;

#pragma unroll 4
    for (int i = 0; i < 16; i++) {
        u64 sxd = s_px[r0 + i];
        u64 syd = s_py[r0 + i];
        u64 szd = s_pz[r0 + i];
        u64 snd = s_pn[r0 + i];
        float rlo = BIGF, rhi = BIGF;
#pragma unroll
        for (int j = 0; j < 4; j++) {
            u64 base = add2(ctn[j], snd);          // nt + ns
            u64 q = fma2(sxd, ctx[j], base);       // -2 sx tx
            q = fma2(syd, cty[j], q);
            q = fma2(szd, ctz[j], q);              // q = d^2 (packed pair)
            float2 qf = u2f(q);
            rlo = fminf(rlo, qf.x);
            rhi = fminf(rhi, qf.y);
            cl[2 * j]     = fminf(cl[2 * j], qf.x);
            cl[2 * j + 1] = fminf(cl[2 * j + 1], qf.y);
        }
        red[(r0 + i) * 17 + txi] = fminf(rlo, rhi);  // row-min partial -> smem now
    }
    __syncthreads();

    // ---- CTA reduction: row mins (across txi), plain store to partials ----
    {
        float m = red[tid * 17];
#pragma unroll
        for (int k = 1; k < 16; k++) m = fminf(m, red[tid * 17 + k]);
        g_rowpart[((long)b * CTILES + blockIdx.x) * N + row0 + tid] = m;
    }
    __syncthreads();

    // ---- CTA reduction: col mins (across tyi) ----
#pragma unroll
    for (int k = 0; k < 8; k++) red[(c0 + k) * 17 + tyi] = cl[k];
    __syncthreads();
    if (tid < TSC) {
        float m = red[tid * 17];
#pragma unroll
        for (int k = 1; k < 16; k++) m = fminf(m, red[tid * 17 + k]);
        g_colpart[((long)b * RTILES + blockIdx.y) * M + col0 + tid] = m;
    }
}

// ---------------- finalize pass 1: reduce partials, block sums ----------------
__global__ void finalize1_kernel(const float* __restrict__ weights) {
    __shared__ float sred[256];
    int tid = blockIdx.x * blockDim.x + threadIdx.x;
    float v;
    if (tid < B * N) {
        int b = tid >> 13, row = tid & 8191;
        const float* p = &g_rowpart[((long)b * CTILES) * N + row];
        float m = p[0];
#pragma unroll 8
        for (int ct = 1; ct < CTILES; ct++) m = fminf(m, p[(long)ct * N]);
        v = sqrtf(m + EPS) * weights[tid] * (1.0f / (B * N));
    } else {
        int t = tid - B * N;
        int b = t >> 13, col = t & 8191;
        const float* p = &g_colpart[((long)b * RTILES) * M + col];
        float m = p[0];
#pragma unroll 8
        for (int rt = 1; rt < RTILES; rt++) m = fminf(m, p[(long)rt * M]);
        v = sqrtf(m + EPS) * (1.0f / (B * M));
    }
    sred[threadIdx.x] = v;
    __syncthreads();
    for (int s = 128; s > 0; s >>= 1) {
        if (threadIdx.x < s) sred[threadIdx.x] += sred[threadIdx.x + s];
        __syncthreads();
    }
    if (threadIdx.x == 0) g_bsum[blockIdx.x] = sred[0];
}

// ---------------- finalize pass 2: single block, plain store ----------------
__global__ void finalize2_kernel(float* __restrict__ out) {
    __shared__ float sred[256];
    sred[threadIdx.x] = g_bsum[threadIdx.x];
    __syncthreads();
    for (int s = 128; s > 0; s >>= 1) {
        if (threadIdx.x < s) sred[threadIdx.x] += sred[threadIdx.x + s];
        __syncthreads();
    }
    if (threadIdx.x == 0) out[0] = sred[0];
}

extern "C" void kernel_launch(void* const* d_in, const int* in_sizes, int n_in,
                              void* d_out, int out_size) {
    const float* source  = (const float*)d_in[0];
    const float* target  = (const float*)d_in[1];
    const float* weights = (const float*)d_in[2];
    float* out = (float*)d_out;

    dim3 grid(M / TSC, N / TSR, B);
    tile_kernel<<<grid, 256>>>(source, target);

    finalize1_kernel<<<(B * N + B * M) / 256, 256>>>(weights);
    finalize2_kernel<<<1, 256>>>(out);
}